// round 3
// baseline (speedup 1.0000x reference)
#include <cuda_runtime.h>
#include <cstdint>

#define HID 128
#define NJOB 100000
#define MAXSRC 20000

// ---------------- scratch (static device globals; no allocation) ----------------
__device__ float g_y[MAXSRC * HID];     // transformed source features for current relation
__device__ float g_acc[NJOB * HID];     // scatter accumulator
__device__ float g_cnt[NJOB];           // per-destination edge counts
__device__ float g_WrS[HID * HID];      // sum of the 5 Wr matrices
__device__ float g_blS[HID];            // sum of the 5 biases

// ---------------- tiny: WrS = sum Wr_r, blS = sum bl_r ----------------
__global__ void sum_wr_kernel(const float* __restrict__ w0, const float* __restrict__ w1,
                              const float* __restrict__ w2, const float* __restrict__ w3,
                              const float* __restrict__ w4,
                              const float* __restrict__ b0, const float* __restrict__ b1,
                              const float* __restrict__ b2, const float* __restrict__ b3,
                              const float* __restrict__ b4)
{
    int i = blockIdx.x * blockDim.x + threadIdx.x;
    if (i < HID * HID) g_WrS[i] = w0[i] + w1[i] + w2[i] + w3[i] + w4[i];
    if (i < HID)       g_blS[i] = b0[i] + b1[i] + b2[i] + b3[i] + b4[i];
}

__global__ void zero4_kernel(float4* __restrict__ p, int n4)
{
    int i = blockIdx.x * blockDim.x + threadIdx.x;
    if (i < n4) p[i] = make_float4(0.f, 0.f, 0.f, 0.f);
}

// ---------------- GEMM: Y[r,c] = sum_k X[r,k] * W[c,k] (+ bias[c]) ----------------
// 128 threads = one output column each; TM=32 rows per block. W staged in shared
// with a 130-float row pitch (conflict-light), X tile in shared (broadcast reads).
// Inner product uses packed fma.rn.f32x2 (even/odd k lanes), final lo+hi add.
__global__ void __launch_bounds__(128) gemm128_kernel(
    const float* __restrict__ X, const float* __restrict__ W,
    const float* __restrict__ bias, float* __restrict__ Y, int nrows)
{
    constexpr int TM = 32;
    extern __shared__ float smem[];
    float* Wsh = smem;              // [128][130]
    float* Xs  = smem + 128 * 130;  // [TM][128]
    const int tid = threadIdx.x;

    #pragma unroll 4
    for (int i = tid; i < HID * HID; i += 128)
        Wsh[(i >> 7) * 130 + (i & 127)] = W[i];

    const int row0 = blockIdx.x * TM;
    #pragma unroll 4
    for (int i = tid; i < TM * HID; i += 128) {
        int r = row0 + (i >> 7);
        Xs[i] = (r < nrows) ? X[r * HID + (i & 127)] : 0.f;
    }
    __syncthreads();

    unsigned long long acc2[TM];
    #pragma unroll
    for (int m = 0; m < TM; m++) acc2[m] = 0ull;

    const unsigned long long* wrow =
        reinterpret_cast<const unsigned long long*>(Wsh + tid * 130);

    for (int k2 = 0; k2 < HID / 2; k2++) {
        unsigned long long w2 = wrow[k2];
        #pragma unroll
        for (int m = 0; m < TM; m++) {
            unsigned long long x2 =
                *reinterpret_cast<const unsigned long long*>(Xs + m * HID + 2 * k2);
            asm("fma.rn.f32x2 %0, %1, %2, %0;" : "+l"(acc2[m]) : "l"(x2), "l"(w2));
        }
    }

    float bv = bias ? bias[tid] : 0.f;
    #pragma unroll
    for (int m = 0; m < TM; m++) {
        int r = row0 + m;
        if (r < nrows) {
            float lo = __uint_as_float((unsigned)(acc2[m] & 0xffffffffull));
            float hi = __uint_as_float((unsigned)(acc2[m] >> 32));
            Y[r * HID + tid] = lo + hi + bv;
        }
    }
}

// ---------------- scatter: one warp per edge, vector fp32 reductions ----------------
__global__ void scatter_kernel(const float* __restrict__ y,
                               const int* __restrict__ src,
                               const int* __restrict__ dst, int nedge)
{
    int g = blockIdx.x * blockDim.x + threadIdx.x;
    int e = g >> 5;
    if (e >= nedge) return;
    int lane = g & 31;
    int s = __ldg(src + e);
    int d = __ldg(dst + e);
    float4 v = __ldg(reinterpret_cast<const float4*>(y + s * HID + lane * 4));
    float* p = g_acc + d * HID + lane * 4;
    asm volatile("red.global.add.v4.f32 [%0], {%1,%2,%3,%4};"
                 :: "l"(p), "f"(v.x), "f"(v.y), "f"(v.z), "f"(v.w) : "memory");
    if (lane == 0) atomicAdd(g_cnt + d, 1.0f);
}

// ---------------- out += acc/max(cnt,1); re-zero acc; optional relu ----------------
__global__ void add_mean_kernel(float* __restrict__ out, int do_relu)
{
    int i = blockIdx.x * blockDim.x + threadIdx.x;
    if (i >= NJOB * (HID / 4)) return;
    int row = i >> 5;
    float c = g_cnt[row];
    float inv = 1.0f / fmaxf(c, 1.0f);

    float4* ap = reinterpret_cast<float4*>(g_acc) + i;
    float4 a = *ap;
    *ap = make_float4(0.f, 0.f, 0.f, 0.f);  // re-zero for next relation (lines stay in L2)

    float4 o = reinterpret_cast<float4*>(out)[i];
    o.x = fmaf(a.x, inv, o.x);
    o.y = fmaf(a.y, inv, o.y);
    o.z = fmaf(a.z, inv, o.z);
    o.w = fmaf(a.w, inv, o.w);
    if (do_relu) {
        o.x = fmaxf(o.x, 0.f); o.y = fmaxf(o.y, 0.f);
        o.z = fmaxf(o.z, 0.f); o.w = fmaxf(o.w, 0.f);
    }
    reinterpret_cast<float4*>(out)[i] = o;
}

// ---------------- host ----------------
extern "C" void kernel_launch(void* const* d_in, const int* in_sizes, int n_in,
                              void* d_out, int out_size)
{
    const float* x_job = (const float*)d_in[0];
    const float* xtab[5];
    xtab[0] = (const float*)d_in[1];  // station
    xtab[1] = (const float*)d_in[1];  // station
    xtab[2] = (const float*)d_in[2];  // machine
    xtab[3] = (const float*)d_in[2];  // machine
    xtab[4] = (const float*)d_in[3];  // robot
    int nsrc[5];
    nsrc[0] = in_sizes[1] / HID; nsrc[1] = nsrc[0];
    nsrc[2] = in_sizes[2] / HID; nsrc[3] = nsrc[2];
    nsrc[4] = in_sizes[3] / HID;

    const int *src[5], *dst[5];
    const float *Wl[5], *bl[5], *Wr[5];
    int nedge[5];
    // Detect input ordering: dict order (src,dst,Wl,bl,Wr per relation) has a
    // 16384-element tensor at index 6; signature order (all src/dst pairs first,
    // then weight triples) has an 800000-element tensor there.
    bool dict = (in_sizes[6] == HID * HID);
    for (int r = 0; r < 5; r++) {
        if (dict) {
            src[r] = (const int*)d_in[4 + 5 * r];
            dst[r] = (const int*)d_in[5 + 5 * r];
            Wl[r]  = (const float*)d_in[6 + 5 * r];
            bl[r]  = (const float*)d_in[7 + 5 * r];
            Wr[r]  = (const float*)d_in[8 + 5 * r];
            nedge[r] = in_sizes[4 + 5 * r];
        } else {
            src[r] = (const int*)d_in[4 + 2 * r];
            dst[r] = (const int*)d_in[5 + 2 * r];
            Wl[r]  = (const float*)d_in[14 + 3 * r];
            bl[r]  = (const float*)d_in[15 + 3 * r];
            Wr[r]  = (const float*)d_in[16 + 3 * r];
            nedge[r] = in_sizes[4 + 2 * r];
        }
    }

    float *yp, *accp, *cntp, *WrSp, *blSp;
    cudaGetSymbolAddress((void**)&yp,   g_y);
    cudaGetSymbolAddress((void**)&accp, g_acc);
    cudaGetSymbolAddress((void**)&cntp, g_cnt);
    cudaGetSymbolAddress((void**)&WrSp, g_WrS);
    cudaGetSymbolAddress((void**)&blSp, g_blS);

    const int SMEM = (128 * 130 + 32 * 128) * (int)sizeof(float);
    cudaFuncSetAttribute(gemm128_kernel, cudaFuncAttributeMaxDynamicSharedMemorySize, SMEM);

    int njob = out_size / HID;

    // Fold all 5 Wr + biases into one matrix/vector.
    sum_wr_kernel<<<64, 256>>>(Wr[0], Wr[1], Wr[2], Wr[3], Wr[4],
                               bl[0], bl[1], bl[2], bl[3], bl[4]);

    // Zero the scatter accumulator once; add_mean re-zeroes it each relation.
    zero4_kernel<<<(NJOB * (HID / 4) + 255) / 256, 256>>>(
        reinterpret_cast<float4*>(accp), NJOB * (HID / 4));

    // Base term: out = x_job @ WrS^T + blS  (also initializes poisoned d_out).
    gemm128_kernel<<<(njob + 31) / 32, 128, SMEM>>>(x_job, WrSp, blSp, (float*)d_out, njob);

    for (int r = 0; r < 5; r++) {
        // y = x_src @ Wl_r^T  (transform BEFORE scatter: 10-20k rows, not 100k)
        gemm128_kernel<<<(nsrc[r] + 31) / 32, 128, SMEM>>>(xtab[r], Wl[r], nullptr, yp, nsrc[r]);
        zero4_kernel<<<(NJOB / 4 + 255) / 256, 256>>>(
            reinterpret_cast<float4*>(cntp), NJOB / 4);
        scatter_kernel<<<((size_t)nedge[r] * 32 + 255) / 256, 256>>>(yp, src[r], dst[r], nedge[r]);
        add_mean_kernel<<<(NJOB * (HID / 4) + 255) / 256, 256>>>((float*)d_out, r == 4 ? 1 : 0);
    }
}

// round 4
// speedup vs baseline: 2.0146x; 2.0146x over previous
#include <cuda_runtime.h>
#include <cstdint>

#define HID 128
#define NJOB 100000
#define MAXSRC 20000
#define MAXY   90000          // 20k+20k+20k+20k+10k source rows
#define EMAX   800000
#define TOTE   (5 * EMAX)
#define NCNT   (5 * NJOB)

// ---------------- scratch (static device globals; no allocation) ----------------
__device__ float g_y[MAXY * HID];       // transformed source feats, all 5 relations
__device__ int   g_icnt[NCNT];          // per (rel, job) edge counts
__device__ int   g_off[NCNT];           // exclusive-scan offsets into g_eidx
__device__ int   g_cur[NCNT];           // fill cursors (copy of g_off)
__device__ int   g_eidx[TOTE];          // CSR payload: row index into g_y
__device__ int   g_bsum[256];           // scan block sums
__device__ float g_WrS[HID * HID];      // sum of the 5 Wr matrices
__device__ float g_blS[HID];            // sum of the 5 biases

// ---------------- tiny: WrS = sum Wr_r, blS = sum bl_r ----------------
__global__ void sum_wr_kernel(const float* __restrict__ w0, const float* __restrict__ w1,
                              const float* __restrict__ w2, const float* __restrict__ w3,
                              const float* __restrict__ w4,
                              const float* __restrict__ b0, const float* __restrict__ b1,
                              const float* __restrict__ b2, const float* __restrict__ b3,
                              const float* __restrict__ b4)
{
    int i = blockIdx.x * blockDim.x + threadIdx.x;
    if (i < HID * HID) g_WrS[i] = w0[i] + w1[i] + w2[i] + w3[i] + w4[i];
    if (i < HID)       g_blS[i] = b0[i] + b1[i] + b2[i] + b3[i] + b4[i];
}

__global__ void zero4_kernel(int4* __restrict__ p, int n4)
{
    int i = blockIdx.x * blockDim.x + threadIdx.x;
    if (i < n4) p[i] = make_int4(0, 0, 0, 0);
}

// ---------------- GEMM: Y[r,c] = sum_k X[r,k] * W[c,k] (+ bias[c]) ----------------
// 256 threads: col = tid&127, row-half = tid>>7; 64 rows per block (32 per half).
// W staged in shared with 130-float pitch; X tile in shared (broadcast reads).
// Inner product uses packed fma.rn.f32x2 over even/odd k lanes.
__global__ void __launch_bounds__(256) gemm128_kernel(
    const float* __restrict__ X, const float* __restrict__ W,
    const float* __restrict__ bias, float* __restrict__ Y, int nrows)
{
    constexpr int TM = 64;          // rows per block
    constexpr int TT = 32;          // rows per thread (TM/2)
    extern __shared__ float smem[];
    float* Wsh = smem;              // [128][130]
    float* Xs  = smem + 128 * 130;  // [TM][128]
    const int tid  = threadIdx.x;
    const int col  = tid & 127;
    const int half = tid >> 7;

    #pragma unroll 4
    for (int i = tid; i < HID * HID; i += 256)
        Wsh[(i >> 7) * 130 + (i & 127)] = W[i];

    const int row0 = blockIdx.x * TM;
    #pragma unroll 4
    for (int i = tid; i < TM * HID; i += 256) {
        int r = row0 + (i >> 7);
        Xs[i] = (r < nrows) ? X[r * HID + (i & 127)] : 0.f;
    }
    __syncthreads();

    unsigned long long acc2[TT];
    #pragma unroll
    for (int m = 0; m < TT; m++) acc2[m] = 0ull;

    const unsigned long long* wrow =
        reinterpret_cast<const unsigned long long*>(Wsh + col * 130);
    const float* xbase = Xs + (half * TT) * HID;

    for (int k2 = 0; k2 < HID / 2; k2++) {
        unsigned long long w2 = wrow[k2];
        #pragma unroll
        for (int m = 0; m < TT; m++) {
            unsigned long long x2 =
                *reinterpret_cast<const unsigned long long*>(xbase + m * HID + 2 * k2);
            asm("fma.rn.f32x2 %0, %1, %2, %0;" : "+l"(acc2[m]) : "l"(x2), "l"(w2));
        }
    }

    float bv = bias ? bias[col] : 0.f;
    #pragma unroll
    for (int m = 0; m < TT; m++) {
        int r = row0 + half * TT + m;
        if (r < nrows) {
            float lo = __uint_as_float((unsigned)(acc2[m] & 0xffffffffull));
            float hi = __uint_as_float((unsigned)(acc2[m] >> 32));
            Y[r * HID + col] = lo + hi + bv;
        }
    }
}

// ---------------- CSR build ----------------
__global__ void hist_kernel(const int* __restrict__ dst, int n, int* __restrict__ cnt)
{
    int i = blockIdx.x * blockDim.x + threadIdx.x;
    if (i < n) atomicAdd(cnt + __ldg(dst + i), 1);
}

// exclusive scan, 3 kernels. scan1: per-block (1024 thr x 4 items) local scan + block sum
__global__ void __launch_bounds__(1024) scan1_kernel(const int* __restrict__ in,
                                                     int* __restrict__ out,
                                                     int* __restrict__ bsum, int n)
{
    __shared__ int sh[1024];
    int base = blockIdx.x * 4096 + threadIdx.x * 4;
    int4 v = make_int4(0, 0, 0, 0);
    if (base < n) v = *reinterpret_cast<const int4*>(in + base);   // n divisible by 4
    int s = v.x + v.y + v.z + v.w;
    sh[threadIdx.x] = s;
    __syncthreads();
    for (int d = 1; d < 1024; d <<= 1) {
        int t = (threadIdx.x >= d) ? sh[threadIdx.x - d] : 0;
        __syncthreads();
        sh[threadIdx.x] += t;
        __syncthreads();
    }
    if (threadIdx.x == 1023) bsum[blockIdx.x] = sh[1023];
    int e = sh[threadIdx.x] - s;                                   // exclusive
    if (base < n) {
        int4 o;
        o.x = e; o.y = e + v.x; o.z = o.y + v.y; o.w = o.z + v.z;
        *reinterpret_cast<int4*>(out + base) = o;
    }
}

__global__ void __launch_bounds__(1024) scan2_kernel(int* __restrict__ bsum, int nb)
{
    __shared__ int sh[1024];
    int v = (threadIdx.x < nb) ? bsum[threadIdx.x] : 0;
    sh[threadIdx.x] = v;
    __syncthreads();
    for (int d = 1; d < 1024; d <<= 1) {
        int t = (threadIdx.x >= d) ? sh[threadIdx.x - d] : 0;
        __syncthreads();
        sh[threadIdx.x] += t;
        __syncthreads();
    }
    if (threadIdx.x < nb) bsum[threadIdx.x] = sh[threadIdx.x] - v; // exclusive
}

// add block bases; also produce cursor copy for the fill pass
__global__ void __launch_bounds__(1024) scan3_kernel(int* __restrict__ out,
                                                     int* __restrict__ cur,
                                                     const int* __restrict__ bsum, int n)
{
    int base = blockIdx.x * 4096 + threadIdx.x * 4;
    if (base < n) {
        int a = bsum[blockIdx.x];
        int4 v = *reinterpret_cast<int4*>(out + base);
        v.x += a; v.y += a; v.z += a; v.w += a;
        *reinterpret_cast<int4*>(out + base) = v;
        *reinterpret_cast<int4*>(cur + base) = v;
    }
}

__global__ void fill_kernel(const int* __restrict__ src, const int* __restrict__ dst,
                            int n, int* __restrict__ cur, int yofs)
{
    int i = blockIdx.x * blockDim.x + threadIdx.x;
    if (i < n) {
        int d = __ldg(dst + i);
        int p = atomicAdd(cur + d, 1);
        g_eidx[p] = yofs + __ldg(src + i);
    }
}

// ---------------- gather: warp per job; 5 relations; mean; +base; relu ----------------
__global__ void __launch_bounds__(256) gather_kernel(const float* __restrict__ y,
                                                     float* __restrict__ out, int njob)
{
    int g = blockIdx.x * blockDim.x + threadIdx.x;
    int j = g >> 5;
    if (j >= njob) return;
    int lane = g & 31;

    float4 tot = reinterpret_cast<const float4*>(out + (size_t)j * HID)[lane]; // base term

    #pragma unroll
    for (int r = 0; r < 5; r++) {
        int idx = r * NJOB + j;
        int c     = __ldg(g_icnt + idx);
        int start = __ldg(g_off  + idx);
        float4 s = make_float4(0.f, 0.f, 0.f, 0.f);
        for (int b = 0; b < c; b += 32) {
            int nn = c - b; if (nn > 32) nn = 32;
            int ei = 0;
            if (lane < nn) ei = __ldg(g_eidx + start + b + lane);
            for (int k = 0; k < nn; k++) {
                int row = __shfl_sync(0xffffffffu, ei, k);
                float4 v = __ldg(reinterpret_cast<const float4*>(y + (size_t)row * HID) + lane);
                s.x += v.x; s.y += v.y; s.z += v.z; s.w += v.w;
            }
        }
        float inv = 1.0f / fmaxf((float)c, 1.0f);
        tot.x = fmaf(s.x, inv, tot.x);
        tot.y = fmaf(s.y, inv, tot.y);
        tot.z = fmaf(s.z, inv, tot.z);
        tot.w = fmaf(s.w, inv, tot.w);
    }
    tot.x = fmaxf(tot.x, 0.f); tot.y = fmaxf(tot.y, 0.f);
    tot.z = fmaxf(tot.z, 0.f); tot.w = fmaxf(tot.w, 0.f);
    reinterpret_cast<float4*>(out + (size_t)j * HID)[lane] = tot;
}

// ---------------- host ----------------
extern "C" void kernel_launch(void* const* d_in, const int* in_sizes, int n_in,
                              void* d_out, int out_size)
{
    const float* x_job = (const float*)d_in[0];
    const float* xtab[5];
    xtab[0] = (const float*)d_in[1];  // station
    xtab[1] = (const float*)d_in[1];  // station
    xtab[2] = (const float*)d_in[2];  // machine
    xtab[3] = (const float*)d_in[2];  // machine
    xtab[4] = (const float*)d_in[3];  // robot
    int nsrc[5];
    nsrc[0] = in_sizes[1] / HID; nsrc[1] = nsrc[0];
    nsrc[2] = in_sizes[2] / HID; nsrc[3] = nsrc[2];
    nsrc[4] = in_sizes[3] / HID;
    int yofs[5];
    yofs[0] = 0;
    for (int r = 1; r < 5; r++) yofs[r] = yofs[r - 1] + nsrc[r - 1];

    const int *src[5], *dst[5];
    const float *Wl[5], *bl[5], *Wr[5];
    int nedge[5];
    // Detect input ordering: dict order (src,dst,Wl,bl,Wr per relation) has a
    // 16384-element tensor at index 6; signature order has 800000 there.
    bool dict = (in_sizes[6] == HID * HID);
    for (int r = 0; r < 5; r++) {
        if (dict) {
            src[r] = (const int*)d_in[4 + 5 * r];
            dst[r] = (const int*)d_in[5 + 5 * r];
            Wl[r]  = (const float*)d_in[6 + 5 * r];
            bl[r]  = (const float*)d_in[7 + 5 * r];
            Wr[r]  = (const float*)d_in[8 + 5 * r];
            nedge[r] = in_sizes[4 + 5 * r];
        } else {
            src[r] = (const int*)d_in[4 + 2 * r];
            dst[r] = (const int*)d_in[5 + 2 * r];
            Wl[r]  = (const float*)d_in[14 + 3 * r];
            bl[r]  = (const float*)d_in[15 + 3 * r];
            Wr[r]  = (const float*)d_in[16 + 3 * r];
            nedge[r] = in_sizes[4 + 2 * r];
        }
    }

    float *yp, *WrSp, *blSp;
    int *icntp, *offp, *curp, *bsump;
    cudaGetSymbolAddress((void**)&yp,    g_y);
    cudaGetSymbolAddress((void**)&WrSp,  g_WrS);
    cudaGetSymbolAddress((void**)&blSp,  g_blS);
    cudaGetSymbolAddress((void**)&icntp, g_icnt);
    cudaGetSymbolAddress((void**)&offp,  g_off);
    cudaGetSymbolAddress((void**)&curp,  g_cur);
    cudaGetSymbolAddress((void**)&bsump, g_bsum);

    const int SMEM = (128 * 130 + 64 * 128) * (int)sizeof(float);
    cudaFuncSetAttribute(gemm128_kernel, cudaFuncAttributeMaxDynamicSharedMemorySize, SMEM);

    int njob = out_size / HID;
    int n5 = 5 * njob;                      // count-array length (divisible by 4)
    int nb = (n5 + 4095) / 4096;            // scan blocks (<= 1024)

    // Fold all 5 Wr + biases into one matrix/vector.
    sum_wr_kernel<<<64, 256>>>(Wr[0], Wr[1], Wr[2], Wr[3], Wr[4],
                               bl[0], bl[1], bl[2], bl[3], bl[4]);

    // Zero per-(rel,job) counters.
    zero4_kernel<<<(n5 / 4 + 255) / 256, 256>>>(reinterpret_cast<int4*>(icntp), n5 / 4);

    // Base term: out = x_job @ WrS^T + blS (also initializes poisoned d_out).
    gemm128_kernel<<<(njob + 63) / 64, 256, SMEM>>>(x_job, WrSp, blSp, (float*)d_out, njob);

    // Transform all source tables: y_r = x_src_r @ Wl_r^T (10-20k rows each).
    for (int r = 0; r < 5; r++)
        gemm128_kernel<<<(nsrc[r] + 63) / 64, 256, SMEM>>>(
            xtab[r], Wl[r], nullptr, yp + (size_t)yofs[r] * HID, nsrc[r]);

    // Histogram destinations per relation.
    for (int r = 0; r < 5; r++)
        hist_kernel<<<(nedge[r] + 255) / 256, 256>>>(dst[r], nedge[r], icntp + r * NJOB);

    // Global exclusive scan over all 5*njob counts (region bases fall out).
    scan1_kernel<<<nb, 1024>>>(icntp, offp, bsump, n5);
    scan2_kernel<<<1, 1024>>>(bsump, nb);
    scan3_kernel<<<nb, 1024>>>(offp, curp, bsump, n5);

    // Fill CSR payload (y-row index, relation offset folded in).
    for (int r = 0; r < 5; r++)
        fill_kernel<<<(nedge[r] + 255) / 256, 256>>>(src[r], dst[r], nedge[r],
                                                     curp + r * NJOB, yofs[r]);

    // Gather + mean + base + relu, one pass.
    gather_kernel<<<(njob * 32 + 255) / 256, 256>>>(yp, (float*)d_out, njob);
}